// round 3
// baseline (speedup 1.0000x reference)
#include <cuda_runtime.h>

// Problem constants (fixed shapes from reference)
#define T_STEPS 2048
#define B_SIZE  4096
#define HID     8
#define OUTD    4
#define LANES_PER_ELEM 8
#define BLOCK_THREADS  256

__device__ __forceinline__ float sigmoid_fast(float x) {
    // 1 / (1 + exp(-x));  EX2 + RCP, ~1e-7 rel err, overflow-safe both directions
    float e = __expf(-x);
    return __fdividef(1.0f, 1.0f + e);
}

__device__ __forceinline__ float tanh_fast(float x) {
    // tanh(x) = sign(x) * (1 - e) / (1 + e), e = exp(-2|x|)  (no overflow)
    float ax = fabsf(x);
    float e  = __expf(-2.0f * ax);
    float r  = __fdividef(1.0f - e, 1.0f + e);
    return copysignf(r, x);
}

// One GRU layer step for this lane's hidden unit.
// Lane `sub` owns gate rows {sub, 8+sub, 16+sub}.
// accR/accZ/accNx arrive prefilled with input-projection partials + biases
// (or just biases when IN_SHFL, in which case vin = own-lane value of the
// input vector, broadcast across the 8-lane group here).
template <bool IN_SHFL>
__device__ __forceinline__ float gru_layer_step(
    float h, float vin,
    float accR, float accZ, float accNx, float bHn,
    const float (&wih)[3][8], const float (&whh)[3][8])
{
    if (IN_SHFL) {
#pragma unroll
        for (int k = 0; k < 8; k++) {
            float vk = __shfl_sync(0xffffffffu, vin, k, LANES_PER_ELEM);
            accR  = fmaf(wih[0][k], vk, accR);
            accZ  = fmaf(wih[1][k], vk, accZ);
            accNx = fmaf(wih[2][k], vk, accNx);
        }
    }
    float accNh = bHn;
#pragma unroll
    for (int k = 0; k < 8; k++) {
        float hk = __shfl_sync(0xffffffffu, h, k, LANES_PER_ELEM);
        accR  = fmaf(whh[0][k], hk, accR);
        accZ  = fmaf(whh[1][k], hk, accZ);
        accNh = fmaf(whh[2][k], hk, accNh);
    }
    float r = sigmoid_fast(accR);
    float z = sigmoid_fast(accZ);
    float n = tanh_fast(fmaf(r, accNh, accNx));
    // (1-z)*n + z*h  ==  n + z*(h-n)
    return fmaf(z, h - n, n);
}

__global__ void __launch_bounds__(BLOCK_THREADS, 1)
gru3_fused_kernel(const float* __restrict__ x,
                  const float* __restrict__ Wih0, const float* __restrict__ Whh0,
                  const float* __restrict__ bih0, const float* __restrict__ bhh0,
                  const float* __restrict__ Wih1, const float* __restrict__ Whh1,
                  const float* __restrict__ bih1, const float* __restrict__ bhh1,
                  const float* __restrict__ Wih2, const float* __restrict__ Whh2,
                  const float* __restrict__ bih2, const float* __restrict__ bhh2,
                  const float* __restrict__ fcW,  const float* __restrict__ fcb,
                  float* __restrict__ out)
{
    const int g   = blockIdx.x * BLOCK_THREADS + threadIdx.x;
    const int b   = g >> 3;       // batch element
    const int sub = g & 7;        // hidden unit owned by this lane

    // ---- load this lane's weight slices into registers ----
    float wih0[3][2], whh0[3][8];
    float wih1[3][8], whh1[3][8];
    float wih2[3][8], whh2[3][8];

#pragma unroll
    for (int gt = 0; gt < 3; gt++) {
        const int row = gt * 8 + sub;
        wih0[gt][0] = Wih0[row * 2 + 0];
        wih0[gt][1] = Wih0[row * 2 + 1];
#pragma unroll
        for (int k = 0; k < 8; k++) {
            whh0[gt][k] = Whh0[row * 8 + k];
            wih1[gt][k] = Wih1[row * 8 + k];
            whh1[gt][k] = Whh1[row * 8 + k];
            wih2[gt][k] = Wih2[row * 8 + k];
            whh2[gt][k] = Whh2[row * 8 + k];
        }
    }
    // biases: r/z gates fold b_ih+b_hh; n gate keeps them split (torch GRU semantics)
    const float bR0  = bih0[sub]      + bhh0[sub];
    const float bZ0  = bih0[8 + sub]  + bhh0[8 + sub];
    const float bXn0 = bih0[16 + sub];
    const float bHn0 = bhh0[16 + sub];
    const float bR1  = bih1[sub]      + bhh1[sub];
    const float bZ1  = bih1[8 + sub]  + bhh1[8 + sub];
    const float bXn1 = bih1[16 + sub];
    const float bHn1 = bhh1[16 + sub];
    const float bR2  = bih2[sub]      + bhh2[sub];
    const float bZ2  = bih2[8 + sub]  + bhh2[8 + sub];
    const float bXn2 = bih2[16 + sub];
    const float bHn2 = bhh2[16 + sub];

    // ---- recurrence state ----
    float h0 = 0.0f, h1 = 0.0f, h2 = 0.0f, acc = 0.0f;

    const float* xb = x + (size_t)b * 2;
    // prefetch t=0
    float x0 = __ldg(xb);
    float x1 = __ldg(xb + 1);

#pragma unroll 1
    for (int t = 0; t < T_STEPS; t++) {
        // prefetch x for t+1 (clamped; result unused on last iter)
        const int tn = (t + 1 < T_STEPS) ? (t + 1) : (T_STEPS - 1);
        const float* xn = xb + (size_t)tn * (B_SIZE * 2);
        float nx0 = __ldg(xn);
        float nx1 = __ldg(xn + 1);

        // layer 0: input proj directly from x (F=2)
        float aR = fmaf(wih0[0][1], x1, fmaf(wih0[0][0], x0, bR0));
        float aZ = fmaf(wih0[1][1], x1, fmaf(wih0[1][0], x0, bZ0));
        float aN = fmaf(wih0[2][1], x1, fmaf(wih0[2][0], x0, bXn0));
        h0 = gru_layer_step<false>(h0, 0.0f, aR, aZ, aN, bHn0, whh0, whh0);

        // layer 1: input = h0(t) broadcast across the 8-lane group
        h1 = gru_layer_step<true>(h1, h0, bR1, bZ1, bXn1, bHn1, wih1, whh1);

        // layer 2: input = h1(t)
        h2 = gru_layer_step<true>(h2, h1, bR2, bZ2, bXn2, bHn2, wih2, whh2);

        acc += h2;
        x0 = nx0; x1 = nx1;
    }

    // ---- mean over T, then FC (OUT=4) ----
    const float mean = acc * (1.0f / (float)T_STEPS);
    float m[8];
#pragma unroll
    for (int k = 0; k < 8; k++)
        m[k] = __shfl_sync(0xffffffffu, mean, k, LANES_PER_ELEM);

    if (sub < OUTD) {
        float o = __ldg(fcb + sub);
#pragma unroll
        for (int k = 0; k < 8; k++)
            o = fmaf(__ldg(fcW + sub * 8 + k), m[k], o);
        out[(size_t)b * OUTD + sub] = o;
    }
}

extern "C" void kernel_launch(void* const* d_in, const int* in_sizes, int n_in,
                              void* d_out, int out_size)
{
    const float* x    = (const float*)d_in[0];
    const float* Wih0 = (const float*)d_in[1];
    const float* Whh0 = (const float*)d_in[2];
    const float* bih0 = (const float*)d_in[3];
    const float* bhh0 = (const float*)d_in[4];
    const float* Wih1 = (const float*)d_in[5];
    const float* Whh1 = (const float*)d_in[6];
    const float* bih1 = (const float*)d_in[7];
    const float* bhh1 = (const float*)d_in[8];
    const float* Wih2 = (const float*)d_in[9];
    const float* Whh2 = (const float*)d_in[10];
    const float* bih2 = (const float*)d_in[11];
    const float* bhh2 = (const float*)d_in[12];
    const float* fcW  = (const float*)d_in[13];
    const float* fcb  = (const float*)d_in[14];
    float* out = (float*)d_out;

    const int total_threads = B_SIZE * LANES_PER_ELEM;        // 32768
    const int blocks = total_threads / BLOCK_THREADS;          // 128

    gru3_fused_kernel<<<blocks, BLOCK_THREADS>>>(
        x,
        Wih0, Whh0, bih0, bhh0,
        Wih1, Whh1, bih1, bhh1,
        Wih2, Whh2, bih2, bhh2,
        fcW, fcb, out);
}